// round 7
// baseline (speedup 1.0000x reference)
#include <cuda_runtime.h>
#include <cuda_bf16.h>
#include <cstdint>
#include <math.h>

#define NB 4
#define NHW 4096
#define NC 256
#define NTOK (NB*NHW)   // 16384

// ================= scratch =================
__device__ __nv_bfloat16 g_xnh[NTOK*NC];
__device__ __nv_bfloat16 g_attnh[NTOK*NC];
__device__ __nv_bfloat16 g_qh[NTOK*NC];
__device__ __nv_bfloat16 g_kh[NTOK*NC];
__device__ __nv_bfloat16 g_vh[NTOK*NC];
__device__ __nv_bfloat16 g_wh[4*NC*NC];
__device__ float g_part[512];
__device__ float g_mean[32];
__device__ float g_rstd[32];

// ================= helpers =================
__device__ __forceinline__ uint32_t smem_to_u32(const void* p) {
    uint32_t a;
    asm("{ .reg .u64 t; cvta.to.shared.u64 t, %1; cvt.u32.u64 %0, t; }" : "=r"(a) : "l"(p));
    return a;
}
#define CP_ASYNC16(saddr, gptr) \
    asm volatile("cp.async.cg.shared.global [%0], [%1], 16;" :: "r"(saddr), "l"(gptr))
#define CP_COMMIT()  asm volatile("cp.async.commit_group;" ::: "memory")
#define CP_WAIT0()   asm volatile("cp.async.wait_group 0;" ::: "memory")
#define CP_WAIT1()   asm volatile("cp.async.wait_group 1;" ::: "memory")

__device__ __forceinline__ void ldsm_x4(uint32_t* r, uint32_t addr) {
    asm volatile("ldmatrix.sync.aligned.m8n8.x4.shared.b16 {%0,%1,%2,%3}, [%4];"
        : "=r"(r[0]), "=r"(r[1]), "=r"(r[2]), "=r"(r[3]) : "r"(addr));
}
__device__ __forceinline__ void ldsm_x4_t(uint32_t* r, uint32_t addr) {
    asm volatile("ldmatrix.sync.aligned.m8n8.x4.trans.shared.b16 {%0,%1,%2,%3}, [%4];"
        : "=r"(r[0]), "=r"(r[1]), "=r"(r[2]), "=r"(r[3]) : "r"(addr));
}
__device__ __forceinline__ void mma16816(float* d, const uint32_t* a, uint32_t b0, uint32_t b1) {
    asm volatile("mma.sync.aligned.m16n8k16.row.col.f32.bf16.bf16.f32 "
        "{%0,%1,%2,%3}, {%4,%5,%6,%7}, {%8,%9}, {%0,%1,%2,%3};"
        : "+f"(d[0]), "+f"(d[1]), "+f"(d[2]), "+f"(d[3])
        : "r"(a[0]), "r"(a[1]), "r"(a[2]), "r"(a[3]), "r"(b0), "r"(b1));
}
__device__ __forceinline__ float ex2f(float x) {
    float y;
    asm("ex2.approx.ftz.f32 %0, %1;" : "=f"(y) : "f"(x));
    return y;
}

// ================= GroupNorm stats (two-stage) =================
__global__ __launch_bounds__(256) void gn_stats1(const float* __restrict__ x) {
    int blk = blockIdx.x;             // 256 blocks = 32 bg x 8 segs
    int bg = blk >> 3, seg = blk & 7;
    int b = bg >> 3, g = bg & 7;
    const float* xb = x + (size_t)b * NHW * NC + (size_t)(seg * 512) * NC + g * 32;
    int t = threadIdx.x;
    float s = 0.f, ss = 0.f;
    for (int idx = t; idx < 4096; idx += 256) {
        int p = idx >> 3, cq = idx & 7;
        float4 v = *(const float4*)(xb + (size_t)p * NC + 4 * cq);
        s  += v.x + v.y + v.z + v.w;
        ss += v.x*v.x + v.y*v.y + v.z*v.z + v.w*v.w;
    }
    __shared__ float rs[256], rq[256];
    rs[t] = s; rq[t] = ss;
    __syncthreads();
    for (int st = 128; st > 0; st >>= 1) {
        if (t < st) { rs[t] += rs[t + st]; rq[t] += rq[t + st]; }
        __syncthreads();
    }
    if (t == 0) { g_part[blk * 2] = rs[0]; g_part[blk * 2 + 1] = rq[0]; }
}

__global__ void gn_stats2() {
    int bg = threadIdx.x;   // 32 threads
    float s = 0.f, ss = 0.f;
#pragma unroll
    for (int i = 0; i < 8; i++) {
        s  += g_part[(bg * 8 + i) * 2];
        ss += g_part[(bg * 8 + i) * 2 + 1];
    }
    float mean = s * (1.f / 131072.f);
    float var  = ss * (1.f / 131072.f) - mean * mean;
    g_mean[bg] = mean;
    g_rstd[bg] = rsqrtf(var + 1e-3f);
}

// ================= GroupNorm apply -> bf16 =================
__global__ __launch_bounds__(256) void gn_norm(const float* __restrict__ x,
                                               const float* __restrict__ gamma,
                                               const float* __restrict__ beta) {
    int i = blockIdx.x * 256 + threadIdx.x;
    int c4  = i & 63;
    int tok = i >> 6;
    int b   = tok >> 12;
    int g   = c4 >> 3;
    float mean = g_mean[b * 8 + g];
    float rstd = g_rstd[b * 8 + g];
    float4 xv = ((const float4*)x)[i];
    float4 ga = ((const float4*)gamma)[c4];
    float4 be = ((const float4*)beta)[c4];
    float o0 = (xv.x - mean) * rstd * ga.x + be.x;
    float o1 = (xv.y - mean) * rstd * ga.y + be.y;
    float o2 = (xv.z - mean) * rstd * ga.z + be.z;
    float o3 = (xv.w - mean) * rstd * ga.w + be.w;
    uint32_t p0, p1;
    asm("cvt.rn.satfinite.bf16x2.f32 %0, %1, %2;" : "=r"(p0) : "f"(o1), "f"(o0));
    asm("cvt.rn.satfinite.bf16x2.f32 %0, %1, %2;" : "=r"(p1) : "f"(o3), "f"(o2));
    *(uint2*)(g_xnh + (size_t)tok * 256 + c4 * 4) = make_uint2(p0, p1);
}

// ================= weight fp32 -> bf16 =================
__global__ __launch_bounds__(256) void conv_w(const float* __restrict__ w0,
                                              const float* __restrict__ w1,
                                              const float* __restrict__ w2,
                                              const float* __restrict__ w3) {
    int i = blockIdx.x * 256 + threadIdx.x;
    int which = i >> 14, off = i & 16383;
    const float* src = which == 0 ? w0 : which == 1 ? w1 : which == 2 ? w2 : w3;
    float4 v = ((const float4*)src)[off];
    uint32_t p0, p1;
    asm("cvt.rn.satfinite.bf16x2.f32 %0, %1, %2;" : "=r"(p0) : "f"(v.y), "f"(v.x));
    asm("cvt.rn.satfinite.bf16x2.f32 %0, %1, %2;" : "=r"(p1) : "f"(v.w), "f"(v.z));
    *(uint2*)(g_wh + (size_t)which * 65536 + off * 4) = make_uint2(p0, p1);
}

// ================= Fused QKV GEMM (512 thr) =================
#define QKV_SMEM (65536 + 2*32768)

__global__ __launch_bounds__(512, 1) void qkv_tc(const __nv_bfloat16* __restrict__ A,
                                                 const __nv_bfloat16* __restrict__ Wh,
                                                 const float* __restrict__ bq,
                                                 const float* __restrict__ bk,
                                                 const float* __restrict__ bv,
                                                 __nv_bfloat16* __restrict__ q,
                                                 __nv_bfloat16* __restrict__ k,
                                                 __nv_bfloat16* __restrict__ v) {
    extern __shared__ char smem[];
    uint32_t sb = smem_to_u32(smem);
    const uint32_t swb = sb + 65536;
    int t = threadIdx.x, lane = t & 31, warp = t >> 5;
    int m0 = blockIdx.x * 128;
    int wm = warp >> 2, wn = warp & 3;

#pragma unroll
    for (int i = 0; i < 8; i++) {
        int g = t + 512 * i;
        int row = g >> 5, j = g & 31;
        int j2 = (j & ~7) | ((j & 7) ^ (row & 7));
        CP_ASYNC16(sb + row * 512 + j2 * 16, A + (size_t)(m0 + row) * 256 + j * 8);
    }
#pragma unroll
    for (int i = 0; i < 4; i++) {
        int g = t + 512 * i;
        int row = g >> 5, j = g & 31;
        int j2 = (j & ~7) | ((j & 7) ^ (row & 7));
        CP_ASYNC16(swb + row * 512 + j2 * 16, Wh + (size_t)row * 256 + j * 8);
    }
    CP_COMMIT();

    const int lrow = lane & 15;
    const int lsel = lane >> 4;
    const int xsw  = lrow & 7;
    const int gid  = lane >> 2, tig = lane & 3;

    float acc[2][8][4];
#pragma unroll
    for (int mt = 0; mt < 2; mt++)
#pragma unroll
        for (int nt = 0; nt < 8; nt++)
#pragma unroll
            for (int e = 0; e < 4; e++) acc[mt][nt][e] = 0.f;

    for (int p = 0; p < 12; p++) {
        if (p < 11) {
            uint32_t dst = swb + ((p + 1) & 1) * 32768;
#pragma unroll
            for (int i = 0; i < 4; i++) {
                int g = t + 512 * i;
                int row = g >> 5, j = g & 31;
                int j2 = (j & ~7) | ((j & 7) ^ (row & 7));
                CP_ASYNC16(dst + row * 512 + j2 * 16,
                           Wh + (size_t)((p + 1) * 64 + row) * 256 + j * 8);
            }
            CP_COMMIT();
            CP_WAIT1();
        } else {
            CP_WAIT0();
        }
        __syncthreads();

        uint32_t wp = swb + (p & 1) * 32768;
        int kp = p & 3;
#pragma unroll
        for (int kk = 0; kk < 4; kk++) {
            int u = kp * 8 + kk * 2 + lsel;
            int us = (u & ~7) | ((u & 7) ^ xsw);
            uint32_t a[2][4];
#pragma unroll
            for (int mt = 0; mt < 2; mt++)
                ldsm_x4(a[mt], sb + (wm * 32 + mt * 16 + lrow) * 512 + us * 16);
#pragma unroll
            for (int ng = 0; ng < 4; ng++) {
                int ub = wn * 8 + ng * 2 + lsel;
                int ubs = (ub & ~7) | ((ub & 7) ^ xsw);
                uint32_t v4[4];
                ldsm_x4_t(v4, wp + (kk * 16 + lrow) * 512 + ubs * 16);
#pragma unroll
                for (int mt = 0; mt < 2; mt++) {
                    mma16816(acc[mt][2 * ng],     a[mt], v4[0], v4[1]);
                    mma16816(acc[mt][2 * ng + 1], a[mt], v4[2], v4[3]);
                }
            }
        }
        __syncthreads();

        if ((p & 3) == 3) {
            int w = p >> 2;
            const float* bw = (w == 0) ? bq : (w == 1) ? bk : bv;
            __nv_bfloat16* ow = (w == 0) ? q : (w == 1) ? k : v;
#pragma unroll
            for (int nt = 0; nt < 8; nt++) {
                int col = wn * 64 + nt * 8 + tig * 2;
                float b0 = bw[col], b1 = bw[col + 1];
#pragma unroll
                for (int mt = 0; mt < 2; mt++) {
#pragma unroll
                    for (int h = 0; h < 2; h++) {
                        int row = m0 + wm * 32 + mt * 16 + gid + 8 * h;
                        float v0 = acc[mt][nt][2 * h]     + b0;
                        float v1 = acc[mt][nt][2 * h + 1] + b1;
                        uint32_t pck;
                        asm("cvt.rn.satfinite.bf16x2.f32 %0, %1, %2;" : "=r"(pck) : "f"(v1), "f"(v0));
                        *(uint32_t*)(ow + (size_t)row * 256 + col) = pck;
                        acc[mt][nt][2 * h] = 0.f; acc[mt][nt][2 * h + 1] = 0.f;
                    }
                }
            }
        }
    }
}

// ================= Tensor-core GEMM (proj) =================
#define GT_SMEM (65536 + 2*16384)

__global__ __launch_bounds__(256, 2) void gemm_tc(const __nv_bfloat16* __restrict__ A,
                                                  const __nv_bfloat16* __restrict__ Wh,
                                                  const float* __restrict__ bias,
                                                  const float* __restrict__ residual,
                                                  float* __restrict__ out) {
    extern __shared__ char smem[];
    uint32_t sb = smem_to_u32(smem);
    const uint32_t sw0 = sb + 65536;
    int t = threadIdx.x, lane = t & 31, warp = t >> 5;
    int n0 = blockIdx.x * 128, m0 = blockIdx.y * 128;
    int wm = warp >> 2, wn = warp & 3;

#pragma unroll
    for (int i = 0; i < 16; i++) {
        int g = t + 256 * i;
        int row = g >> 5, j = g & 31;
        int j2 = (j & ~7) | ((j & 7) ^ (row & 7));
        CP_ASYNC16(sb + row * 512 + j2 * 16, A + (size_t)(m0 + row) * 256 + j * 8);
    }
#pragma unroll
    for (int i = 0; i < 4; i++) {
        int g = t + 256 * i;
        int row = g >> 4, j = g & 15;
        int j2 = (j & ~7) | ((j & 7) ^ (row & 7));
        CP_ASYNC16(sw0 + row * 256 + j2 * 16, Wh + (size_t)row * 256 + n0 + j * 8);
    }
    CP_COMMIT();

    const int lrow = lane & 15;
    const int lsel = lane >> 4;
    const int xsw  = lrow & 7;
    const uint32_t arow = sb + (wm * 64 + lrow) * 512;

    float acc[4][4][4];
#pragma unroll
    for (int mt = 0; mt < 4; mt++)
#pragma unroll
        for (int nt = 0; nt < 4; nt++)
#pragma unroll
            for (int e = 0; e < 4; e++) acc[mt][nt][e] = 0.f;

    for (int kp = 0; kp < 4; kp++) {
        if (kp < 3) {
            uint32_t dst = sw0 + ((kp + 1) & 1) * 16384;
#pragma unroll
            for (int i = 0; i < 4; i++) {
                int g = t + 256 * i;
                int row = g >> 4, j = g & 15;
                int j2 = (j & ~7) | ((j & 7) ^ (row & 7));
                CP_ASYNC16(dst + row * 256 + j2 * 16,
                           Wh + (size_t)((kp + 1) * 64 + row) * 256 + n0 + j * 8);
            }
            CP_COMMIT();
            CP_WAIT1();
        } else {
            CP_WAIT0();
        }
        __syncthreads();

        uint32_t wp = sw0 + (kp & 1) * 16384;
#pragma unroll
        for (int kk = 0; kk < 4; kk++) {
            int u = kp * 8 + kk * 2 + lsel;
            int us = (u & ~7) | ((u & 7) ^ xsw);
            uint32_t a[4][4];
#pragma unroll
            for (int mt = 0; mt < 4; mt++)
                ldsm_x4(a[mt], arow + mt * 16 * 512 + us * 16);
#pragma unroll
            for (int ng = 0; ng < 2; ng++) {
                int ub = wn * 4 + ng * 2 + lsel;
                int ubs = (ub & ~7) | ((ub & 7) ^ xsw);
                uint32_t v4[4];
                ldsm_x4_t(v4, wp + (kk * 16 + lrow) * 256 + ubs * 16);
#pragma unroll
                for (int mt = 0; mt < 4; mt++) {
                    mma16816(acc[mt][2 * ng],     a[mt], v4[0], v4[1]);
                    mma16816(acc[mt][2 * ng + 1], a[mt], v4[2], v4[3]);
                }
            }
        }
        __syncthreads();
    }

    int gid = lane >> 2, tig = lane & 3;
#pragma unroll
    for (int nt = 0; nt < 4; nt++) {
        int col = n0 + wn * 32 + nt * 8 + tig * 2;
        float b0 = bias[col], b1 = bias[col + 1];
#pragma unroll
        for (int mt = 0; mt < 4; mt++) {
#pragma unroll
            for (int h = 0; h < 2; h++) {
                int row = m0 + wm * 64 + mt * 16 + gid + 8 * h;
                size_t off = (size_t)row * 256 + col;
                float2 rr = *(const float2*)(residual + off);
                *(float2*)(out + off) = make_float2(acc[mt][nt][2 * h] + b0 + rr.x,
                                                    acc[mt][nt][2 * h + 1] + b1 + rr.y);
            }
        }
    }
}

// ================= Flash attention v3: split-phase, smem-traffic-minimized =================
// 256 thr, 8 warps. a=warp>>1 (32-row block), bh=warp&1 (S: key-half / PV: d-half).
// S: warp 32x32. P via 16KB smem (pair-synced). PV: warp 32 rows x 128 d.
// SMEM: Q[128][256] @0 (64KB); KV buf0 @65536, buf1 @131072 (K 32KB + V 32KB each);
//       P @196608 (16KB, row stride 128B, unit-swizzled); l @212992 (1KB).
#define FLP 196608
#define FLL 212992
#define FL_SMEM 214016
#define EX2C 0.09016844f   // 0.0625 * log2(e)

__device__ __forceinline__ void load_kv(uint32_t sdst, const __nv_bfloat16* Kt,
                                        const __nv_bfloat16* Vt, int t) {
#pragma unroll
    for (int i = 0; i < 8; i++) {
        int g = t + 256 * i;
        int row = g >> 5, j = g & 31;
        int j2 = (j & ~7) | ((j & 7) ^ (row & 7));
        CP_ASYNC16(sdst + row * 512 + j2 * 16, Kt + row * 256 + j * 8);
        CP_ASYNC16(sdst + 32768 + row * 512 + j2 * 16, Vt + row * 256 + j * 8);
    }
}

__global__ __launch_bounds__(256, 1) void flash_mma(const __nv_bfloat16* __restrict__ Qh,
                                                    const __nv_bfloat16* __restrict__ Kh,
                                                    const __nv_bfloat16* __restrict__ Vh,
                                                    __nv_bfloat16* __restrict__ Oh) {
    extern __shared__ char smem[];
    uint32_t sb = smem_to_u32(smem);
    int t = threadIdx.x, lane = t & 31, warp = t >> 5;
    int a = warp >> 1, bh = warp & 1;
    int b = blockIdx.y, qt = blockIdx.x;

    const __nv_bfloat16* Qg = Qh + ((size_t)b * NHW + qt * 128) * NC;
    const __nv_bfloat16* Kb = Kh + (size_t)b * NHW * NC;
    const __nv_bfloat16* Vb = Vh + (size_t)b * NHW * NC;

#pragma unroll
    for (int i = 0; i < 16; i++) {
        int g = t + 256 * i;
        int row = g >> 5, j = g & 31;
        int j2 = (j & ~7) | ((j & 7) ^ (row & 7));
        CP_ASYNC16(sb + row * 512 + j2 * 16, Qg + row * 256 + j * 8);
    }
    load_kv(sb + 65536, Kb, Vb, t);
    CP_COMMIT();

    const int lrow = lane & 15;
    const int lsel = lane >> 4;
    const int xsw  = lrow & 7;
    const int gid  = lane >> 2, tig = lane & 3;
    const uint32_t qrow0 = sb + (a * 32 + lrow) * 512;
    const uint32_t qrow1 = qrow0 + 16 * 512;
    const uint32_t Pb = sb + FLP;

    float o[2][16][4];
#pragma unroll
    for (int rb = 0; rb < 2; rb++)
#pragma unroll
        for (int nt = 0; nt < 16; nt++)
#pragma unroll
            for (int e = 0; e < 4; e++) o[rb][nt][e] = 0.f;
    float lacc[4] = {0.f, 0.f, 0.f, 0.f};

    for (int kt = 0; kt < 64; kt++) {
        if (kt < 63) {
            load_kv(sb + 65536 + ((kt + 1) & 1) * 65536,
                    Kb + (size_t)(kt + 1) * 64 * NC, Vb + (size_t)(kt + 1) * 64 * NC, t);
            CP_COMMIT();
            CP_WAIT1();
        } else {
            CP_WAIT0();
        }
        __syncthreads();

        uint32_t kvb = sb + 65536 + (kt & 1) * 65536;

        // ---- S = Q K^T : warp computes 32 rows (32a..) x 32 keys (32bh..) ----
        float s[8][4];
#pragma unroll
        for (int j = 0; j < 8; j++)
#pragma unroll
            for (int e = 0; e < 4; e++) s[j][e] = 0.f;
#pragma unroll
        for (int kc = 0; kc < 16; kc++) {
            int u = kc * 2 + lsel;
            int us = (u & ~7) | ((u & 7) ^ xsw);
            uint32_t a0[4], a1[4], kb0[4], kb1[4];
            ldsm_x4(a0, qrow0 + us * 16);
            ldsm_x4(a1, qrow1 + us * 16);
            ldsm_x4(kb0, kvb + (bh * 32 + lrow) * 512 + us * 16);
            ldsm_x4(kb1, kvb + (bh * 32 + 16 + lrow) * 512 + us * 16);
            mma16816(s[0], a0, kb0[0], kb0[2]);
            mma16816(s[1], a0, kb0[1], kb0[3]);
            mma16816(s[2], a0, kb1[0], kb1[2]);
            mma16816(s[3], a0, kb1[1], kb1[3]);
            mma16816(s[4], a1, kb0[0], kb0[2]);
            mma16816(s[5], a1, kb0[1], kb0[3]);
            mma16816(s[6], a1, kb1[0], kb1[2]);
            mma16816(s[7], a1, kb1[1], kb1[3]);
        }

        // ---- exp + pack + store P (16B-unit swizzled by row) ----
#pragma unroll
        for (int rb = 0; rb < 2; rb++) {
#pragma unroll
            for (int g = 0; g < 4; g++) {
                int idx = rb * 4 + g;
                float e0 = ex2f(s[idx][0] * EX2C);
                float e1 = ex2f(s[idx][1] * EX2C);
                float e2 = ex2f(s[idx][2] * EX2C);
                float e3 = ex2f(s[idx][3] * EX2C);
                lacc[rb * 2]     += e0 + e1;
                lacc[rb * 2 + 1] += e2 + e3;
                uint32_t p01, p23;
                asm("cvt.rn.satfinite.bf16x2.f32 %0, %1, %2;" : "=r"(p01) : "f"(e1), "f"(e0));
                asm("cvt.rn.satfinite.bf16x2.f32 %0, %1, %2;" : "=r"(p23) : "f"(e3), "f"(e2));
                int unit = bh * 4 + g;
                int row0 = a * 32 + rb * 16 + gid;
                int row1 = row0 + 8;
                uint32_t a0 = Pb + row0 * 128 + ((unit ^ (row0 & 7)) * 16) + tig * 4;
                uint32_t a1 = Pb + row1 * 128 + ((unit ^ (row1 & 7)) * 16) + tig * 4;
                asm volatile("st.shared.b32 [%0], %1;" :: "r"(a0), "r"(p01) : "memory");
                asm volatile("st.shared.b32 [%0], %1;" :: "r"(a1), "r"(p23) : "memory");
            }
        }
        // pair barrier: warps (2a, 2a+1) both finished writing P rows 32a..32a+32
        asm volatile("bar.sync %0, 64;" :: "r"(a + 1) : "memory");

        // ---- O += P V : warp computes 32 rows x 128 d (cols 128*bh..) ----
#pragma unroll
        for (int kc2 = 0; kc2 < 4; kc2++) {
            int pr0 = a * 32 + lrow;
            int pr1 = pr0 + 16;
            int pu = kc2 * 2 + lsel;
            uint32_t pa0[4], pa1[4];
            ldsm_x4(pa0, Pb + pr0 * 128 + ((pu ^ (pr0 & 7)) * 16));
            ldsm_x4(pa1, Pb + pr1 * 128 + ((pu ^ (pr1 & 7)) * 16));
            uint32_t vrow = kvb + 32768 + (kc2 * 16 + lrow) * 512;
#pragma unroll
            for (int ng = 0; ng < 8; ng++) {
                int u = bh * 16 + ng * 2 + lsel;
                int us = (u & ~7) | ((u & 7) ^ xsw);
                uint32_t v4[4];
                ldsm_x4_t(v4, vrow + us * 16);
                mma16816(o[0][2 * ng],     pa0, v4[0], v4[1]);
                mma16816(o[0][2 * ng + 1], pa0, v4[2], v4[3]);
                mma16816(o[1][2 * ng],     pa1, v4[0], v4[1]);
                mma16816(o[1][2 * ng + 1], pa1, v4[2], v4[3]);
            }
        }
        __syncthreads();
    }

    // ---- l: quad-reduce then combine across key-halves via smem ----
#pragma unroll
    for (int h = 0; h < 4; h++) {
        lacc[h] += __shfl_xor_sync(0xffffffffu, lacc[h], 1);
        lacc[h] += __shfl_xor_sync(0xffffffffu, lacc[h], 2);
    }
    float* lr = (float*)(smem + (FLL - 0));
    if (tig == 0) {
        lr[(a * 32 + gid) * 2 + bh]      = lacc[0];
        lr[(a * 32 + gid + 8) * 2 + bh]  = lacc[1];
        lr[(a * 32 + 16 + gid) * 2 + bh] = lacc[2];
        lr[(a * 32 + 24 + gid) * 2 + bh] = lacc[3];
    }
    __syncthreads();

#pragma unroll
    for (int rb = 0; rb < 2; rb++) {
        int row0 = a * 32 + rb * 16 + gid;
        float i0 = 1.f / (lr[row0 * 2] + lr[row0 * 2 + 1]);
        float i1 = 1.f / (lr[(row0 + 8) * 2] + lr[(row0 + 8) * 2 + 1]);
        __nv_bfloat16* O0 = Oh + ((size_t)b * NHW + qt * 128 + row0) * NC + bh * 128;
#pragma unroll
        for (int nt = 0; nt < 16; nt++) {
            uint32_t p0, p1;
            float a0 = o[rb][nt][0] * i0, a1 = o[rb][nt][1] * i0;
            float a2 = o[rb][nt][2] * i1, a3 = o[rb][nt][3] * i1;
            asm("cvt.rn.satfinite.bf16x2.f32 %0, %1, %2;" : "=r"(p0) : "f"(a1), "f"(a0));
            asm("cvt.rn.satfinite.bf16x2.f32 %0, %1, %2;" : "=r"(p1) : "f"(a3), "f"(a2));
            *(uint32_t*)(O0 + nt * 8 + tig * 2) = p0;
            *(uint32_t*)(O0 + 8 * NC + nt * 8 + tig * 2) = p1;
        }
    }
}

// ================= launch =================
extern "C" void kernel_launch(void* const* d_in, const int* in_sizes, int n_in,
                              void* d_out, int out_size) {
    const float* x     = (const float*)d_in[0];
    const float* gamma = (const float*)d_in[1];
    const float* beta  = (const float*)d_in[2];
    const float* wq    = (const float*)d_in[3];
    const float* bq    = (const float*)d_in[4];
    const float* wk    = (const float*)d_in[5];
    const float* bk    = (const float*)d_in[6];
    const float* wv    = (const float*)d_in[7];
    const float* bv    = (const float*)d_in[8];
    const float* wp    = (const float*)d_in[9];
    const float* bp    = (const float*)d_in[10];
    float* out = (float*)d_out;

    __nv_bfloat16 *p_xnh, *p_attnh, *p_qh, *p_kh, *p_vh, *p_wh;
    cudaGetSymbolAddress((void**)&p_xnh,   g_xnh);
    cudaGetSymbolAddress((void**)&p_attnh, g_attnh);
    cudaGetSymbolAddress((void**)&p_qh,    g_qh);
    cudaGetSymbolAddress((void**)&p_kh,    g_kh);
    cudaGetSymbolAddress((void**)&p_vh,    g_vh);
    cudaGetSymbolAddress((void**)&p_wh,    g_wh);

    cudaFuncSetAttribute(flash_mma, cudaFuncAttributeMaxDynamicSharedMemorySize, FL_SMEM);
    cudaFuncSetAttribute(qkv_tc,    cudaFuncAttributeMaxDynamicSharedMemorySize, QKV_SMEM);
    cudaFuncSetAttribute(gemm_tc,   cudaFuncAttributeMaxDynamicSharedMemorySize, GT_SMEM);

    gn_stats1<<<256, 256>>>(x);
    gn_stats2<<<1, 32>>>();
    gn_norm<<<4096, 256>>>(x, gamma, beta);
    conv_w<<<256, 256>>>(wq, wk, wv, wp);

    qkv_tc<<<128, 512, QKV_SMEM>>>(p_xnh, p_wh, bq, bk, bv, p_qh, p_kh, p_vh);

    flash_mma<<<dim3(32, 4), 256, FL_SMEM>>>(p_qh, p_kh, p_vh, p_attnh);

    gemm_tc<<<dim3(2, 128), 256, GT_SMEM>>>(p_attnh, p_wh + 196608, bp, x, out);
}

// round 8
// speedup vs baseline: 1.0760x; 1.0760x over previous
#include <cuda_runtime.h>
#include <cuda_bf16.h>
#include <cstdint>
#include <math.h>

#define NB 4
#define NHW 4096
#define NC 256
#define NTOK (NB*NHW)   // 16384

// ================= scratch =================
__device__ __nv_bfloat16 g_xnh[NTOK*NC];
__device__ __nv_bfloat16 g_attnh[NTOK*NC];
__device__ __nv_bfloat16 g_qh[NTOK*NC];
__device__ __nv_bfloat16 g_kh[NTOK*NC];
__device__ __nv_bfloat16 g_vh[NTOK*NC];
__device__ __nv_bfloat16 g_wh[4*NC*NC];   // bf16 wq|wk|wv|wp
__device__ float g_part[512];

// ================= helpers =================
__device__ __forceinline__ uint32_t smem_to_u32(const void* p) {
    uint32_t a;
    asm("{ .reg .u64 t; cvta.to.shared.u64 t, %1; cvt.u32.u64 %0, t; }" : "=r"(a) : "l"(p));
    return a;
}
#define CP_ASYNC16(saddr, gptr) \
    asm volatile("cp.async.cg.shared.global [%0], [%1], 16;" :: "r"(saddr), "l"(gptr))
#define CP_COMMIT()  asm volatile("cp.async.commit_group;" ::: "memory")
#define CP_WAIT0()   asm volatile("cp.async.wait_group 0;" ::: "memory")
#define CP_WAIT1()   asm volatile("cp.async.wait_group 1;" ::: "memory")

__device__ __forceinline__ void ldsm_x4(uint32_t* r, uint32_t addr) {
    asm volatile("ldmatrix.sync.aligned.m8n8.x4.shared.b16 {%0,%1,%2,%3}, [%4];"
        : "=r"(r[0]), "=r"(r[1]), "=r"(r[2]), "=r"(r[3]) : "r"(addr));
}
__device__ __forceinline__ void ldsm_x4_t(uint32_t* r, uint32_t addr) {
    asm volatile("ldmatrix.sync.aligned.m8n8.x4.trans.shared.b16 {%0,%1,%2,%3}, [%4];"
        : "=r"(r[0]), "=r"(r[1]), "=r"(r[2]), "=r"(r[3]) : "r"(addr));
}
__device__ __forceinline__ void mma16816(float* d, const uint32_t* a, uint32_t b0, uint32_t b1) {
    asm volatile("mma.sync.aligned.m16n8k16.row.col.f32.bf16.bf16.f32 "
        "{%0,%1,%2,%3}, {%4,%5,%6,%7}, {%8,%9}, {%0,%1,%2,%3};"
        : "+f"(d[0]), "+f"(d[1]), "+f"(d[2]), "+f"(d[3])
        : "r"(a[0]), "r"(a[1]), "r"(a[2]), "r"(a[3]), "r"(b0), "r"(b1));
}
__device__ __forceinline__ float ex2f(float x) {
    float y;
    asm("ex2.approx.ftz.f32 %0, %1;" : "=f"(y) : "f"(x));
    return y;
}

// ================= Stage 1: GN partial sums (blocks 0-255) + weight convert (blocks 256-511) =================
__global__ __launch_bounds__(256) void gn_stats_convw(const float* __restrict__ x,
                                                      const float* __restrict__ w0,
                                                      const float* __restrict__ w1,
                                                      const float* __restrict__ w2,
                                                      const float* __restrict__ w3) {
    int blk = blockIdx.x;
    int t = threadIdx.x;
    if (blk >= 256) {
        // weight fp32 -> bf16
        int i = (blk - 256) * 256 + t;     // float4 index, 65536 total
        int which = i >> 14, off = i & 16383;
        const float* src = which == 0 ? w0 : which == 1 ? w1 : which == 2 ? w2 : w3;
        float4 v = ((const float4*)src)[off];
        uint32_t p0, p1;
        asm("cvt.rn.satfinite.bf16x2.f32 %0, %1, %2;" : "=r"(p0) : "f"(v.y), "f"(v.x));
        asm("cvt.rn.satfinite.bf16x2.f32 %0, %1, %2;" : "=r"(p1) : "f"(v.w), "f"(v.z));
        *(uint2*)(g_wh + (size_t)which * 65536 + off * 4) = make_uint2(p0, p1);
        return;
    }
    int bg = blk >> 3, seg = blk & 7;
    int b = bg >> 3, g = bg & 7;
    const float* xb = x + (size_t)b * NHW * NC + (size_t)(seg * 512) * NC + g * 32;
    float s = 0.f, ss = 0.f;
    for (int idx = t; idx < 4096; idx += 256) {
        int p = idx >> 3, cq = idx & 7;
        float4 v = *(const float4*)(xb + (size_t)p * NC + 4 * cq);
        s  += v.x + v.y + v.z + v.w;
        ss += v.x*v.x + v.y*v.y + v.z*v.z + v.w*v.w;
    }
    __shared__ float rs[256], rq[256];
    rs[t] = s; rq[t] = ss;
    __syncthreads();
    for (int st = 128; st > 0; st >>= 1) {
        if (t < st) { rs[t] += rs[t + st]; rq[t] += rq[t + st]; }
        __syncthreads();
    }
    if (t == 0) { g_part[blk * 2] = rs[0]; g_part[blk * 2 + 1] = rq[0]; }
}

// ================= GN apply (inline final reduce) -> bf16 =================
__global__ __launch_bounds__(256) void gn_norm(const float* __restrict__ x,
                                               const float* __restrict__ gamma,
                                               const float* __restrict__ beta) {
    __shared__ float sm_mean[32], sm_rstd[32];
    int t = threadIdx.x;
    if (t < 32) {
        float s = 0.f, ss = 0.f;
#pragma unroll
        for (int i = 0; i < 8; i++) {
            s  += g_part[(t * 8 + i) * 2];
            ss += g_part[(t * 8 + i) * 2 + 1];
        }
        float mean = s * (1.f / 131072.f);
        float var  = ss * (1.f / 131072.f) - mean * mean;
        sm_mean[t] = mean;
        sm_rstd[t] = rsqrtf(var + 1e-3f);
    }
    __syncthreads();
    int i = blockIdx.x * 256 + t;
    int c4  = i & 63;
    int tok = i >> 6;
    int b   = tok >> 12;
    int g   = c4 >> 3;
    float mean = sm_mean[b * 8 + g];
    float rstd = sm_rstd[b * 8 + g];
    float4 xv = ((const float4*)x)[i];
    float4 ga = ((const float4*)gamma)[c4];
    float4 be = ((const float4*)beta)[c4];
    float o0 = (xv.x - mean) * rstd * ga.x + be.x;
    float o1 = (xv.y - mean) * rstd * ga.y + be.y;
    float o2 = (xv.z - mean) * rstd * ga.z + be.z;
    float o3 = (xv.w - mean) * rstd * ga.w + be.w;
    uint32_t p0, p1;
    asm("cvt.rn.satfinite.bf16x2.f32 %0, %1, %2;" : "=r"(p0) : "f"(o1), "f"(o0));
    asm("cvt.rn.satfinite.bf16x2.f32 %0, %1, %2;" : "=r"(p1) : "f"(o3), "f"(o2));
    *(uint2*)(g_xnh + (size_t)tok * 256 + c4 * 4) = make_uint2(p0, p1);
}

// ================= Fused QKV GEMM: 256 thr, 8 warps = 2Mx4N, warp tile 64x64 =================
// A[128][256] resident (64KB); 12 x 64-row W panels double-buffered (2x32KB).
#define QKV_SMEM (65536 + 2*32768)

__global__ __launch_bounds__(256, 1) void qkv_tc(const __nv_bfloat16* __restrict__ A,
                                                 const __nv_bfloat16* __restrict__ Wh,
                                                 const float* __restrict__ bq,
                                                 const float* __restrict__ bk,
                                                 const float* __restrict__ bv,
                                                 __nv_bfloat16* __restrict__ q,
                                                 __nv_bfloat16* __restrict__ k,
                                                 __nv_bfloat16* __restrict__ v) {
    extern __shared__ char smem[];
    uint32_t sb = smem_to_u32(smem);
    const uint32_t swb = sb + 65536;
    int t = threadIdx.x, lane = t & 31, warp = t >> 5;
    int m0 = blockIdx.x * 128;
    int wm = warp >> 2, wn = warp & 3;

    // A tile [128][256] swizzled (16 float4 per thread) + W panel 0 (8 per thread)
#pragma unroll
    for (int i = 0; i < 16; i++) {
        int g = t + 256 * i;
        int row = g >> 5, j = g & 31;
        int j2 = (j & ~7) | ((j & 7) ^ (row & 7));
        CP_ASYNC16(sb + row * 512 + j2 * 16, A + (size_t)(m0 + row) * 256 + j * 8);
    }
#pragma unroll
    for (int i = 0; i < 8; i++) {
        int g = t + 256 * i;
        int row = g >> 5, j = g & 31;
        int j2 = (j & ~7) | ((j & 7) ^ (row & 7));
        CP_ASYNC16(swb + row * 512 + j2 * 16, Wh + (size_t)row * 256 + j * 8);
    }
    CP_COMMIT();

    const int lrow = lane & 15;
    const int lsel = lane >> 4;
    const int xsw  = lrow & 7;
    const int gid  = lane >> 2, tig = lane & 3;

    float acc[4][8][4];
#pragma unroll
    for (int mt = 0; mt < 4; mt++)
#pragma unroll
        for (int nt = 0; nt < 8; nt++)
#pragma unroll
            for (int e = 0; e < 4; e++) acc[mt][nt][e] = 0.f;

    for (int p = 0; p < 12; p++) {
        if (p < 11) {
            uint32_t dst = swb + ((p + 1) & 1) * 32768;
#pragma unroll
            for (int i = 0; i < 8; i++) {
                int g = t + 256 * i;
                int row = g >> 5, j = g & 31;
                int j2 = (j & ~7) | ((j & 7) ^ (row & 7));
                CP_ASYNC16(dst + row * 512 + j2 * 16,
                           Wh + (size_t)((p + 1) * 64 + row) * 256 + j * 8);
            }
            CP_COMMIT();
            CP_WAIT1();
        } else {
            CP_WAIT0();
        }
        __syncthreads();

        uint32_t wp = swb + (p & 1) * 32768;
        int kp = p & 3;
#pragma unroll
        for (int kk = 0; kk < 4; kk++) {
            int u = kp * 8 + kk * 2 + lsel;
            int us = (u & ~7) | ((u & 7) ^ xsw);
            uint32_t a[4][4];
#pragma unroll
            for (int mt = 0; mt < 4; mt++)
                ldsm_x4(a[mt], sb + (wm * 64 + mt * 16 + lrow) * 512 + us * 16);
#pragma unroll
            for (int ng = 0; ng < 4; ng++) {
                int ub = wn * 8 + ng * 2 + lsel;
                int ubs = (ub & ~7) | ((ub & 7) ^ xsw);
                uint32_t v4[4];
                ldsm_x4_t(v4, wp + (kk * 16 + lrow) * 512 + ubs * 16);
#pragma unroll
                for (int mt = 0; mt < 4; mt++) {
                    mma16816(acc[mt][2 * ng],     a[mt], v4[0], v4[1]);
                    mma16816(acc[mt][2 * ng + 1], a[mt], v4[2], v4[3]);
                }
            }
        }
        __syncthreads();

        if ((p & 3) == 3) {
            int w = p >> 2;
            const float* bw = (w == 0) ? bq : (w == 1) ? bk : bv;
            __nv_bfloat16* ow = (w == 0) ? q : (w == 1) ? k : v;
#pragma unroll
            for (int nt = 0; nt < 8; nt++) {
                int col = wn * 64 + nt * 8 + tig * 2;
                float b0 = bw[col], b1 = bw[col + 1];
#pragma unroll
                for (int mt = 0; mt < 4; mt++) {
#pragma unroll
                    for (int h = 0; h < 2; h++) {
                        int row = m0 + wm * 64 + mt * 16 + gid + 8 * h;
                        float v0 = acc[mt][nt][2 * h]     + b0;
                        float v1 = acc[mt][nt][2 * h + 1] + b1;
                        uint32_t pck;
                        asm("cvt.rn.satfinite.bf16x2.f32 %0, %1, %2;" : "=r"(pck) : "f"(v1), "f"(v0));
                        *(uint32_t*)(ow + (size_t)row * 256 + col) = pck;
                        acc[mt][nt][2 * h] = 0.f; acc[mt][nt][2 * h + 1] = 0.f;
                    }
                }
            }
        }
    }
}

// ================= Proj GEMM: same shape, 4 panels, +bias +residual, fp32 out =================
#define GT_SMEM (65536 + 2*32768)

__global__ __launch_bounds__(256, 1) void gemm_tc(const __nv_bfloat16* __restrict__ A,
                                                  const __nv_bfloat16* __restrict__ Wh,
                                                  const float* __restrict__ bias,
                                                  const float* __restrict__ residual,
                                                  float* __restrict__ out) {
    extern __shared__ char smem[];
    uint32_t sb = smem_to_u32(smem);
    const uint32_t swb = sb + 65536;
    int t = threadIdx.x, lane = t & 31, warp = t >> 5;
    int m0 = blockIdx.x * 128;
    int wm = warp >> 2, wn = warp & 3;

#pragma unroll
    for (int i = 0; i < 16; i++) {
        int g = t + 256 * i;
        int row = g >> 5, j = g & 31;
        int j2 = (j & ~7) | ((j & 7) ^ (row & 7));
        CP_ASYNC16(sb + row * 512 + j2 * 16, A + (size_t)(m0 + row) * 256 + j * 8);
    }
#pragma unroll
    for (int i = 0; i < 8; i++) {
        int g = t + 256 * i;
        int row = g >> 5, j = g & 31;
        int j2 = (j & ~7) | ((j & 7) ^ (row & 7));
        CP_ASYNC16(swb + row * 512 + j2 * 16, Wh + (size_t)row * 256 + j * 8);
    }
    CP_COMMIT();

    const int lrow = lane & 15;
    const int lsel = lane >> 4;
    const int xsw  = lrow & 7;
    const int gid  = lane >> 2, tig = lane & 3;

    float acc[4][8][4];
#pragma unroll
    for (int mt = 0; mt < 4; mt++)
#pragma unroll
        for (int nt = 0; nt < 8; nt++)
#pragma unroll
            for (int e = 0; e < 4; e++) acc[mt][nt][e] = 0.f;

    for (int p = 0; p < 4; p++) {
        if (p < 3) {
            uint32_t dst = swb + ((p + 1) & 1) * 32768;
#pragma unroll
            for (int i = 0; i < 8; i++) {
                int g = t + 256 * i;
                int row = g >> 5, j = g & 31;
                int j2 = (j & ~7) | ((j & 7) ^ (row & 7));
                CP_ASYNC16(dst + row * 512 + j2 * 16,
                           Wh + (size_t)((p + 1) * 64 + row) * 256 + j * 8);
            }
            CP_COMMIT();
            CP_WAIT1();
        } else {
            CP_WAIT0();
        }
        __syncthreads();

        uint32_t wp = swb + (p & 1) * 32768;
#pragma unroll
        for (int kk = 0; kk < 4; kk++) {
            int u = p * 8 + kk * 2 + lsel;
            int us = (u & ~7) | ((u & 7) ^ xsw);
            uint32_t a[4][4];
#pragma unroll
            for (int mt = 0; mt < 4; mt++)
                ldsm_x4(a[mt], sb + (wm * 64 + mt * 16 + lrow) * 512 + us * 16);
#pragma unroll
            for (int ng = 0; ng < 4; ng++) {
                int ub = wn * 8 + ng * 2 + lsel;
                int ubs = (ub & ~7) | ((ub & 7) ^ xsw);
                uint32_t v4[4];
                ldsm_x4_t(v4, wp + (kk * 16 + lrow) * 512 + ubs * 16);
#pragma unroll
                for (int mt = 0; mt < 4; mt++) {
                    mma16816(acc[mt][2 * ng],     a[mt], v4[0], v4[1]);
                    mma16816(acc[mt][2 * ng + 1], a[mt], v4[2], v4[3]);
                }
            }
        }
        __syncthreads();
    }

#pragma unroll
    for (int nt = 0; nt < 8; nt++) {
        int col = wn * 64 + nt * 8 + tig * 2;
        float b0 = bias[col], b1 = bias[col + 1];
#pragma unroll
        for (int mt = 0; mt < 4; mt++) {
#pragma unroll
            for (int h = 0; h < 2; h++) {
                int row = m0 + wm * 64 + mt * 16 + gid + 8 * h;
                size_t off = (size_t)row * 256 + col;
                float2 rr = *(const float2*)(residual + off);
                *(float2*)(out + off) = make_float2(acc[mt][nt][2 * h] + b0 + rr.x,
                                                    acc[mt][nt][2 * h + 1] + b1 + rr.y);
            }
        }
    }
}

// ================= Flash attention (R4 structure, EX2C fold) =================
#define FL_SMEM (192*1024)
#define EX2C 0.09016844f   // 0.0625 * log2(e)

__device__ __forceinline__ void load_kv(uint32_t sdst, const __nv_bfloat16* Kt,
                                        const __nv_bfloat16* Vt, int t) {
#pragma unroll
    for (int i = 0; i < 8; i++) {
        int g = t + 256 * i;
        int row = g >> 5, j = g & 31;
        int j2 = (j & ~7) | ((j & 7) ^ (row & 7));
        CP_ASYNC16(sdst + row * 512 + j2 * 16, Kt + row * 256 + j * 8);
        CP_ASYNC16(sdst + 32768 + row * 512 + j2 * 16, Vt + row * 256 + j * 8);
    }
}

__global__ __launch_bounds__(256, 1) void flash_mma(const __nv_bfloat16* __restrict__ Qh,
                                                    const __nv_bfloat16* __restrict__ Kh,
                                                    const __nv_bfloat16* __restrict__ Vh,
                                                    __nv_bfloat16* __restrict__ Oh) {
    extern __shared__ char smem[];
    uint32_t sb = smem_to_u32(smem);
    int t = threadIdx.x, lane = t & 31, warp = t >> 5;
    int b = blockIdx.y, qt = blockIdx.x;

    const __nv_bfloat16* Qg = Qh + ((size_t)b * NHW + qt * 128) * NC;
    const __nv_bfloat16* Kb = Kh + (size_t)b * NHW * NC;
    const __nv_bfloat16* Vb = Vh + (size_t)b * NHW * NC;

#pragma unroll
    for (int i = 0; i < 16; i++) {
        int g = t + 256 * i;
        int row = g >> 5, j = g & 31;
        int j2 = (j & ~7) | ((j & 7) ^ (row & 7));
        CP_ASYNC16(sb + row * 512 + j2 * 16, Qg + row * 256 + j * 8);
    }
    load_kv(sb + 65536, Kb, Vb, t);
    CP_COMMIT();

    const int lrow = lane & 15;
    const int lsel = lane >> 4;
    const int xsw  = lrow & 7;
    const uint32_t qrow = sb + (warp * 16 + lrow) * 512;

    float o[32][4];
#pragma unroll
    for (int nt = 0; nt < 32; nt++)
#pragma unroll
        for (int e = 0; e < 4; e++) o[nt][e] = 0.f;
    float l0 = 0.f, l1 = 0.f;

    for (int kt = 0; kt < 64; kt++) {
        if (kt < 63) {
            load_kv(sb + 65536 + ((kt + 1) & 1) * 65536,
                    Kb + (size_t)(kt + 1) * 64 * NC, Vb + (size_t)(kt + 1) * 64 * NC, t);
            CP_COMMIT();
            CP_WAIT1();
        } else {
            CP_WAIT0();
        }
        __syncthreads();

        uint32_t kvb = sb + 65536 + (kt & 1) * 65536;

        float s[8][4];
#pragma unroll
        for (int j = 0; j < 8; j++)
#pragma unroll
            for (int e = 0; e < 4; e++) s[j][e] = 0.f;
#pragma unroll
        for (int kc = 0; kc < 16; kc++) {
            int u = kc * 2 + lsel;
            int us = (u & ~7) | ((u & 7) ^ xsw);
            uint32_t a[4];
            ldsm_x4(a, qrow + us * 16);
#pragma unroll
            for (int g4 = 0; g4 < 4; g4++) {
                uint32_t kb[4];
                ldsm_x4(kb, kvb + (g4 * 16 + lrow) * 512 + us * 16);
                mma16816(s[2 * g4],     a, kb[0], kb[2]);
                mma16816(s[2 * g4 + 1], a, kb[1], kb[3]);
            }
        }

        uint32_t pa[4][4];
#pragma unroll
        for (int j = 0; j < 8; j++) {
            float e0 = ex2f(s[j][0] * EX2C);
            float e1 = ex2f(s[j][1] * EX2C);
            float e2 = ex2f(s[j][2] * EX2C);
            float e3 = ex2f(s[j][3] * EX2C);
            l0 += e0 + e1; l1 += e2 + e3;
            uint32_t p01, p23;
            asm("cvt.rn.satfinite.bf16x2.f32 %0, %1, %2;" : "=r"(p01) : "f"(e1), "f"(e0));
            asm("cvt.rn.satfinite.bf16x2.f32 %0, %1, %2;" : "=r"(p23) : "f"(e3), "f"(e2));
            pa[j >> 1][(j & 1) * 2]     = p01;
            pa[j >> 1][(j & 1) * 2 + 1] = p23;
        }

        uint32_t vbase = kvb + 32768;
#pragma unroll
        for (int kc2 = 0; kc2 < 4; kc2++) {
            uint32_t vrow = vbase + (kc2 * 16 + lrow) * 512;
#pragma unroll
            for (int ng = 0; ng < 16; ng++) {
                int u = ng * 2 + lsel;
                int us = (u & ~7) | ((u & 7) ^ xsw);
                uint32_t v4[4];
                ldsm_x4_t(v4, vrow + us * 16);
                mma16816(o[2 * ng],     pa[kc2], v4[0], v4[1]);
                mma16816(o[2 * ng + 1], pa[kc2], v4[2], v4[3]);
            }
        }
        __syncthreads();
    }

    l0 += __shfl_xor_sync(0xffffffffu, l0, 1);
    l0 += __shfl_xor_sync(0xffffffffu, l0, 2);
    l1 += __shfl_xor_sync(0xffffffffu, l1, 1);
    l1 += __shfl_xor_sync(0xffffffffu, l1, 2);
    float i0 = 1.f / l0, i1 = 1.f / l1;

    int gid = lane >> 2, tig = lane & 3;
    int row0 = qt * 128 + warp * 16 + gid;
    __nv_bfloat16* O0 = Oh + ((size_t)b * NHW + row0) * NC;
#pragma unroll
    for (int nt = 0; nt < 32; nt++) {
        uint32_t p0, p1;
        float a0 = o[nt][0] * i0, a1 = o[nt][1] * i0;
        float a2 = o[nt][2] * i1, a3 = o[nt][3] * i1;
        asm("cvt.rn.satfinite.bf16x2.f32 %0, %1, %2;" : "=r"(p0) : "f"(a1), "f"(a0));
        asm("cvt.rn.satfinite.bf16x2.f32 %0, %1, %2;" : "=r"(p1) : "f"(a3), "f"(a2));
        *(uint32_t*)(O0 + nt * 8 + tig * 2) = p0;
        *(uint32_t*)(O0 + 8 * NC + nt * 8 + tig * 2) = p1;
    }
}

// ================= launch =================
extern "C" void kernel_launch(void* const* d_in, const int* in_sizes, int n_in,
                              void* d_out, int out_size) {
    const float* x     = (const float*)d_in[0];
    const float* gamma = (const float*)d_in[1];
    const float* beta  = (const float*)d_in[2];
    const float* wq    = (const float*)d_in[3];
    const float* bq    = (const float*)d_in[4];
    const float* wk    = (const float*)d_in[5];
    const float* bk    = (const float*)d_in[6];
    const float* wv    = (const float*)d_in[7];
    const float* bv    = (const float*)d_in[8];
    const float* wp    = (const float*)d_in[9];
    const float* bp    = (const float*)d_in[10];
    float* out = (float*)d_out;

    __nv_bfloat16 *p_xnh, *p_attnh, *p_qh, *p_kh, *p_vh, *p_wh;
    cudaGetSymbolAddress((void**)&p_xnh,   g_xnh);
    cudaGetSymbolAddress((void**)&p_attnh, g_attnh);
    cudaGetSymbolAddress((void**)&p_qh,    g_qh);
    cudaGetSymbolAddress((void**)&p_kh,    g_kh);
    cudaGetSymbolAddress((void**)&p_vh,    g_vh);
    cudaGetSymbolAddress((void**)&p_wh,    g_wh);

    cudaFuncSetAttribute(flash_mma, cudaFuncAttributeMaxDynamicSharedMemorySize, FL_SMEM);
    cudaFuncSetAttribute(qkv_tc,    cudaFuncAttributeMaxDynamicSharedMemorySize, QKV_SMEM);
    cudaFuncSetAttribute(gemm_tc,   cudaFuncAttributeMaxDynamicSharedMemorySize, GT_SMEM);

    gn_stats_convw<<<512, 256>>>(x, wq, wk, wv, wp);
    gn_norm<<<4096, 256>>>(x, gamma, beta);

    qkv_tc<<<128, 256, QKV_SMEM>>>(p_xnh, p_wh, bq, bk, bv, p_qh, p_kh, p_vh);

    flash_mma<<<dim3(32, 4), 256, FL_SMEM>>>(p_qh, p_kh, p_vh, p_attnh);

    gemm_tc<<<128, 256, GT_SMEM>>>(p_attnh, p_wh + 196608, bp, x, out);
}

// round 12
// speedup vs baseline: 1.1288x; 1.0490x over previous
#include <cuda_runtime.h>
#include <cuda_bf16.h>
#include <cstdint>
#include <math.h>

#define NB 4
#define NHW 4096
#define NC 256
#define NTOK (NB*NHW)   // 16384

// ================= scratch =================
__device__ __nv_bfloat16 g_attnh[NTOK*NC];
__device__ __nv_bfloat16 g_qh[NTOK*NC];
__device__ __nv_bfloat16 g_kh[NTOK*NC];
__device__ __nv_bfloat16 g_vh[NTOK*NC];
__device__ __nv_bfloat16 g_wh[4*NC*NC];   // bf16 wq|wk|wv|wp
__device__ float g_part[512];

// ================= helpers =================
__device__ __forceinline__ uint32_t smem_to_u32(const void* p) {
    uint32_t a;
    asm("{ .reg .u64 t; cvta.to.shared.u64 t, %1; cvt.u32.u64 %0, t; }" : "=r"(a) : "l"(p));
    return a;
}
#define CP_ASYNC16(saddr, gptr) \
    asm volatile("cp.async.cg.shared.global [%0], [%1], 16;" :: "r"(saddr), "l"(gptr))
#define CP_COMMIT()  asm volatile("cp.async.commit_group;" ::: "memory")
#define CP_WAIT0()   asm volatile("cp.async.wait_group 0;" ::: "memory")
#define CP_WAIT1()   asm volatile("cp.async.wait_group 1;" ::: "memory")

__device__ __forceinline__ void ldsm_x4(uint32_t* r, uint32_t addr) {
    asm volatile("ldmatrix.sync.aligned.m8n8.x4.shared.b16 {%0,%1,%2,%3}, [%4];"
        : "=r"(r[0]), "=r"(r[1]), "=r"(r[2]), "=r"(r[3]) : "r"(addr));
}
__device__ __forceinline__ void ldsm_x4_t(uint32_t* r, uint32_t addr) {
    asm volatile("ldmatrix.sync.aligned.m8n8.x4.trans.shared.b16 {%0,%1,%2,%3}, [%4];"
        : "=r"(r[0]), "=r"(r[1]), "=r"(r[2]), "=r"(r[3]) : "r"(addr));
}
__device__ __forceinline__ void mma16816(float* d, const uint32_t* a, uint32_t b0, uint32_t b1) {
    asm volatile("mma.sync.aligned.m16n8k16.row.col.f32.bf16.bf16.f32 "
        "{%0,%1,%2,%3}, {%4,%5,%6,%7}, {%8,%9}, {%0,%1,%2,%3};"
        : "+f"(d[0]), "+f"(d[1]), "+f"(d[2]), "+f"(d[3])
        : "r"(a[0]), "r"(a[1]), "r"(a[2]), "r"(a[3]), "r"(b0), "r"(b1));
}
__device__ __forceinline__ float ex2f(float x) {
    float y;
    asm("ex2.approx.ftz.f32 %0, %1;" : "=f"(y) : "f"(x));
    return y;
}

// ================= Stage 1: GN partial sums (blocks 0-255) + weight convert (blocks 256-511) =================
__global__ __launch_bounds__(256) void gn_stats_convw(const float* __restrict__ x,
                                                      const float* __restrict__ w0,
                                                      const float* __restrict__ w1,
                                                      const float* __restrict__ w2,
                                                      const float* __restrict__ w3) {
    int blk = blockIdx.x;
    int t = threadIdx.x;
    if (blk >= 256) {
        int i = (blk - 256) * 256 + t;
        int which = i >> 14, off = i & 16383;
        const float* src = which == 0 ? w0 : which == 1 ? w1 : which == 2 ? w2 : w3;
        float4 v = ((const float4*)src)[off];
        uint32_t p0, p1;
        asm("cvt.rn.satfinite.bf16x2.f32 %0, %1, %2;" : "=r"(p0) : "f"(v.y), "f"(v.x));
        asm("cvt.rn.satfinite.bf16x2.f32 %0, %1, %2;" : "=r"(p1) : "f"(v.w), "f"(v.z));
        *(uint2*)(g_wh + (size_t)which * 65536 + off * 4) = make_uint2(p0, p1);
        return;
    }
    int bg = blk >> 3, seg = blk & 7;
    int b = bg >> 3, g = bg & 7;
    const float* xb = x + (size_t)b * NHW * NC + (size_t)(seg * 512) * NC + g * 32;
    float s = 0.f, ss = 0.f;
    for (int idx = t; idx < 4096; idx += 256) {
        int p = idx >> 3, cq = idx & 7;
        float4 v = *(const float4*)(xb + (size_t)p * NC + 4 * cq);
        s  += v.x + v.y + v.z + v.w;
        ss += v.x*v.x + v.y*v.y + v.z*v.z + v.w*v.w;
    }
    __shared__ float rs[256], rq[256];
    rs[t] = s; rq[t] = ss;
    __syncthreads();
    for (int st = 128; st > 0; st >>= 1) {
        if (t < st) { rs[t] += rs[t + st]; rq[t] += rq[t + st]; }
        __syncthreads();
    }
    if (t == 0) { g_part[blk * 2] = rs[0]; g_part[blk * 2 + 1] = rq[0]; }
}

// ================= Fused GroupNorm-apply + QKV GEMM =================
// A tile built in-kernel: LDG x fp32, normalize (stats re-reduced from g_part), STS bf16 swizzled.
// 8 warps = 2Mx4N, warp tile 64x64; 12 x 64-row W panels double-buffered.
#define QKV_SMEM (65536 + 2*32768 + 256)

__global__ __launch_bounds__(256, 1) void qkv_tc(const float* __restrict__ x,
                                                 const float* __restrict__ gamma,
                                                 const float* __restrict__ beta,
                                                 const __nv_bfloat16* __restrict__ Wh,
                                                 const float* __restrict__ bq,
                                                 const float* __restrict__ bk,
                                                 const float* __restrict__ bv,
                                                 __nv_bfloat16* __restrict__ q,
                                                 __nv_bfloat16* __restrict__ k,
                                                 __nv_bfloat16* __restrict__ v) {
    extern __shared__ char smem[];
    uint32_t sb = smem_to_u32(smem);
    const uint32_t swb = sb + 65536;
    float* sm_stat = (float*)(smem + 131072);   // mean[8], rstd[8]
    int t = threadIdx.x, lane = t & 31, warp = t >> 5;
    int m0 = blockIdx.x * 128;
    int batch = blockIdx.x >> 5;
    int wm = warp >> 2, wn = warp & 3;

    // prefetch W panel 0
#pragma unroll
    for (int i = 0; i < 8; i++) {
        int g = t + 256 * i;
        int row = g >> 5, j = g & 31;
        int j2 = (j & ~7) | ((j & 7) ^ (row & 7));
        CP_ASYNC16(swb + row * 512 + j2 * 16, Wh + (size_t)row * 256 + j * 8);
    }
    CP_COMMIT();

    // stats for this batch (re-reduce partials; g_part is tiny & L2-hot)
    if (t < 8) {
        int bg = batch * 8 + t;
        float s = 0.f, ss = 0.f;
#pragma unroll
        for (int i = 0; i < 8; i++) {
            s  += g_part[(bg * 8 + i) * 2];
            ss += g_part[(bg * 8 + i) * 2 + 1];
        }
        float mean = s * (1.f / 131072.f);
        float var  = ss * (1.f / 131072.f) - mean * mean;
        sm_stat[t] = mean;
        sm_stat[8 + t] = rsqrtf(var + 1e-3f);
    }
    __syncthreads();

    // build normalized bf16 A tile directly in smem
    const float4* xg = (const float4*)(x + (size_t)m0 * 256);
    const float4* ga4 = (const float4*)gamma;
    const float4* be4 = (const float4*)beta;
#pragma unroll
    for (int i = 0; i < 32; i++) {
        int idx = t + 256 * i;              // 8192 float4
        int row = idx >> 6, c4 = idx & 63;
        int g = c4 >> 3;
        float mean = sm_stat[g], rstd = sm_stat[8 + g];
        float4 xv = xg[idx];
        float4 ga = ga4[c4], be = be4[c4];
        float o0 = (xv.x - mean) * rstd * ga.x + be.x;
        float o1 = (xv.y - mean) * rstd * ga.y + be.y;
        float o2 = (xv.z - mean) * rstd * ga.z + be.z;
        float o3 = (xv.w - mean) * rstd * ga.w + be.w;
        uint32_t p0, p1;
        asm("cvt.rn.satfinite.bf16x2.f32 %0, %1, %2;" : "=r"(p0) : "f"(o1), "f"(o0));
        asm("cvt.rn.satfinite.bf16x2.f32 %0, %1, %2;" : "=r"(p1) : "f"(o3), "f"(o2));
        int j = c4 >> 1;
        int j2 = (j & ~7) | ((j & 7) ^ (row & 7));
        *(uint2*)(smem + (row * 512 + j2 * 16 + (c4 & 1) * 8)) = make_uint2(p0, p1);
    }

    const int lrow = lane & 15;
    const int lsel = lane >> 4;
    const int xsw  = lrow & 7;
    const int gid  = lane >> 2, tig = lane & 3;

    float acc[4][8][4];
#pragma unroll
    for (int mt = 0; mt < 4; mt++)
#pragma unroll
        for (int nt = 0; nt < 8; nt++)
#pragma unroll
            for (int e = 0; e < 4; e++) acc[mt][nt][e] = 0.f;

    for (int p = 0; p < 12; p++) {
        if (p < 11) {
            uint32_t dst = swb + ((p + 1) & 1) * 32768;
#pragma unroll
            for (int i = 0; i < 8; i++) {
                int g = t + 256 * i;
                int row = g >> 5, j = g & 31;
                int j2 = (j & ~7) | ((j & 7) ^ (row & 7));
                CP_ASYNC16(dst + row * 512 + j2 * 16,
                           Wh + (size_t)((p + 1) * 64 + row) * 256 + j * 8);
            }
            CP_COMMIT();
            CP_WAIT1();
        } else {
            CP_WAIT0();
        }
        __syncthreads();

        uint32_t wp = swb + (p & 1) * 32768;
        int kp = p & 3;
#pragma unroll
        for (int kk = 0; kk < 4; kk++) {
            int u = kp * 8 + kk * 2 + lsel;
            int us = (u & ~7) | ((u & 7) ^ xsw);
            uint32_t a[4][4];
#pragma unroll
            for (int mt = 0; mt < 4; mt++)
                ldsm_x4(a[mt], sb + (wm * 64 + mt * 16 + lrow) * 512 + us * 16);
#pragma unroll
            for (int ng = 0; ng < 4; ng++) {
                int ub = wn * 8 + ng * 2 + lsel;
                int ubs = (ub & ~7) | ((ub & 7) ^ xsw);
                uint32_t v4[4];
                ldsm_x4_t(v4, wp + (kk * 16 + lrow) * 512 + ubs * 16);
#pragma unroll
                for (int mt = 0; mt < 4; mt++) {
                    mma16816(acc[mt][2 * ng],     a[mt], v4[0], v4[1]);
                    mma16816(acc[mt][2 * ng + 1], a[mt], v4[2], v4[3]);
                }
            }
        }
        __syncthreads();

        if ((p & 3) == 3) {
            int w = p >> 2;
            const float* bw = (w == 0) ? bq : (w == 1) ? bk : bv;
            __nv_bfloat16* ow = (w == 0) ? q : (w == 1) ? k : v;
#pragma unroll
            for (int nt = 0; nt < 8; nt++) {
                int col = wn * 64 + nt * 8 + tig * 2;
                float b0 = bw[col], b1 = bw[col + 1];
#pragma unroll
                for (int mt = 0; mt < 4; mt++) {
#pragma unroll
                    for (int h = 0; h < 2; h++) {
                        int row = m0 + wm * 64 + mt * 16 + gid + 8 * h;
                        float v0 = acc[mt][nt][2 * h]     + b0;
                        float v1 = acc[mt][nt][2 * h + 1] + b1;
                        uint32_t pck;
                        asm("cvt.rn.satfinite.bf16x2.f32 %0, %1, %2;" : "=r"(pck) : "f"(v1), "f"(v0));
                        *(uint32_t*)(ow + (size_t)row * 256 + col) = pck;
                        acc[mt][nt][2 * h] = 0.f; acc[mt][nt][2 * h + 1] = 0.f;
                    }
                }
            }
        }
    }
}

// ================= Proj GEMM (+bias +residual, fp32 out) =================
#define GT_SMEM (65536 + 2*32768)

__global__ __launch_bounds__(256, 1) void gemm_tc(const __nv_bfloat16* __restrict__ A,
                                                  const __nv_bfloat16* __restrict__ Wh,
                                                  const float* __restrict__ bias,
                                                  const float* __restrict__ residual,
                                                  float* __restrict__ out) {
    extern __shared__ char smem[];
    uint32_t sb = smem_to_u32(smem);
    const uint32_t swb = sb + 65536;
    int t = threadIdx.x, lane = t & 31, warp = t >> 5;
    int m0 = blockIdx.x * 128;
    int wm = warp >> 2, wn = warp & 3;

#pragma unroll
    for (int i = 0; i < 16; i++) {
        int g = t + 256 * i;
        int row = g >> 5, j = g & 31;
        int j2 = (j & ~7) | ((j & 7) ^ (row & 7));
        CP_ASYNC16(sb + row * 512 + j2 * 16, A + (size_t)(m0 + row) * 256 + j * 8);
    }
#pragma unroll
    for (int i = 0; i < 8; i++) {
        int g = t + 256 * i;
        int row = g >> 5, j = g & 31;
        int j2 = (j & ~7) | ((j & 7) ^ (row & 7));
        CP_ASYNC16(swb + row * 512 + j2 * 16, Wh + (size_t)row * 256 + j * 8);
    }
    CP_COMMIT();

    const int lrow = lane & 15;
    const int lsel = lane >> 4;
    const int xsw  = lrow & 7;
    const int gid  = lane >> 2, tig = lane & 3;

    float acc[4][8][4];
#pragma unroll
    for (int mt = 0; mt < 4; mt++)
#pragma unroll
        for (int nt = 0; nt < 8; nt++)
#pragma unroll
            for (int e = 0; e < 4; e++) acc[mt][nt][e] = 0.f;

    for (int p = 0; p < 4; p++) {
        if (p < 3) {
            uint32_t dst = swb + ((p + 1) & 1) * 32768;
#pragma unroll
            for (int i = 0; i < 8; i++) {
                int g = t + 256 * i;
                int row = g >> 5, j = g & 31;
                int j2 = (j & ~7) | ((j & 7) ^ (row & 7));
                CP_ASYNC16(dst + row * 512 + j2 * 16,
                           Wh + (size_t)((p + 1) * 64 + row) * 256 + j * 8);
            }
            CP_COMMIT();
            CP_WAIT1();
        } else {
            CP_WAIT0();
        }
        __syncthreads();

        uint32_t wp = swb + (p & 1) * 32768;
#pragma unroll
        for (int kk = 0; kk < 4; kk++) {
            int u = p * 8 + kk * 2 + lsel;
            int us = (u & ~7) | ((u & 7) ^ xsw);
            uint32_t a[4][4];
#pragma unroll
            for (int mt = 0; mt < 4; mt++)
                ldsm_x4(a[mt], sb + (wm * 64 + mt * 16 + lrow) * 512 + us * 16);
#pragma unroll
            for (int ng = 0; ng < 4; ng++) {
                int ub = wn * 8 + ng * 2 + lsel;
                int ubs = (ub & ~7) | ((ub & 7) ^ xsw);
                uint32_t v4[4];
                ldsm_x4_t(v4, wp + (kk * 16 + lrow) * 512 + ubs * 16);
#pragma unroll
                for (int mt = 0; mt < 4; mt++) {
                    mma16816(acc[mt][2 * ng],     a[mt], v4[0], v4[1]);
                    mma16816(acc[mt][2 * ng + 1], a[mt], v4[2], v4[3]);
                }
            }
        }
        __syncthreads();
    }

#pragma unroll
    for (int nt = 0; nt < 8; nt++) {
        int col = wn * 64 + nt * 8 + tig * 2;
        float b0 = bias[col], b1 = bias[col + 1];
#pragma unroll
        for (int mt = 0; mt < 4; mt++) {
#pragma unroll
            for (int h = 0; h < 2; h++) {
                int row = m0 + wm * 64 + mt * 16 + gid + 8 * h;
                size_t off = (size_t)row * 256 + col;
                float2 rr = *(const float2*)(residual + off);
                *(float2*)(out + off) = make_float2(acc[mt][nt][2 * h] + b0 + rr.x,
                                                    acc[mt][nt][2 * h + 1] + b1 + rr.y);
            }
        }
    }
}

// ================= Flash attention (R8-proven: 256 thr, P in registers, syncthreads) =================
#define FL_SMEM (192*1024)
#define EX2C 0.09016844f   // 0.0625 * log2(e)

__device__ __forceinline__ void load_kv(uint32_t sdst, const __nv_bfloat16* Kt,
                                        const __nv_bfloat16* Vt, int t) {
#pragma unroll
    for (int i = 0; i < 8; i++) {
        int g = t + 256 * i;
        int row = g >> 5, j = g & 31;
        int j2 = (j & ~7) | ((j & 7) ^ (row & 7));
        CP_ASYNC16(sdst + row * 512 + j2 * 16, Kt + row * 256 + j * 8);
        CP_ASYNC16(sdst + 32768 + row * 512 + j2 * 16, Vt + row * 256 + j * 8);
    }
}

__global__ __launch_bounds__(256, 1) void flash_mma(const __nv_bfloat16* __restrict__ Qh,
                                                    const __nv_bfloat16* __restrict__ Kh,
                                                    const __nv_bfloat16* __restrict__ Vh,
                                                    __nv_bfloat16* __restrict__ Oh) {
    extern __shared__ char smem[];
    uint32_t sb = smem_to_u32(smem);
    int t = threadIdx.x, lane = t & 31, warp = t >> 5;
    int b = blockIdx.y, qt = blockIdx.x;

    const __nv_bfloat16* Qg = Qh + ((size_t)b * NHW + qt * 128) * NC;
    const __nv_bfloat16* Kb = Kh + (size_t)b * NHW * NC;
    const __nv_bfloat16* Vb = Vh + (size_t)b * NHW * NC;

#pragma unroll
    for (int i = 0; i < 16; i++) {
        int g = t + 256 * i;
        int row = g >> 5, j = g & 31;
        int j2 = (j & ~7) | ((j & 7) ^ (row & 7));
        CP_ASYNC16(sb + row * 512 + j2 * 16, Qg + row * 256 + j * 8);
    }
    load_kv(sb + 65536, Kb, Vb, t);
    CP_COMMIT();

    const int lrow = lane & 15;
    const int lsel = lane >> 4;
    const int xsw  = lrow & 7;
    const uint32_t qrow = sb + (warp * 16 + lrow) * 512;

    float o[32][4];
#pragma unroll
    for (int nt = 0; nt < 32; nt++)
#pragma unroll
        for (int e = 0; e < 4; e++) o[nt][e] = 0.f;
    float l0 = 0.f, l1 = 0.f;

    for (int kt = 0; kt < 64; kt++) {
        if (kt < 63) {
            load_kv(sb + 65536 + ((kt + 1) & 1) * 65536,
                    Kb + (size_t)(kt + 1) * 64 * NC, Vb + (size_t)(kt + 1) * 64 * NC, t);
            CP_COMMIT();
            CP_WAIT1();
        } else {
            CP_WAIT0();
        }
        __syncthreads();

        uint32_t kvb = sb + 65536 + (kt & 1) * 65536;

        float s[8][4];
#pragma unroll
        for (int j = 0; j < 8; j++)
#pragma unroll
            for (int e = 0; e < 4; e++) s[j][e] = 0.f;
#pragma unroll
        for (int kc = 0; kc < 16; kc++) {
            int u = kc * 2 + lsel;
            int us = (u & ~7) | ((u & 7) ^ xsw);
            uint32_t a[4];
            ldsm_x4(a, qrow + us * 16);
#pragma unroll
            for (int g4 = 0; g4 < 4; g4++) {
                uint32_t kb[4];
                ldsm_x4(kb, kvb + (g4 * 16 + lrow) * 512 + us * 16);
                mma16816(s[2 * g4],     a, kb[0], kb[2]);
                mma16816(s[2 * g4 + 1], a, kb[1], kb[3]);
            }
        }

        uint32_t pa[4][4];
#pragma unroll
        for (int j = 0; j < 8; j++) {
            float e0 = ex2f(s[j][0] * EX2C);
            float e1 = ex2f(s[j][1] * EX2C);
            float e2 = ex2f(s[j][2] * EX2C);
            float e3 = ex2f(s[j][3] * EX2C);
            l0 += e0 + e1; l1 += e2 + e3;
            uint32_t p01, p23;
            asm("cvt.rn.satfinite.bf16x2.f32 %0, %1, %2;" : "=r"(p01) : "f"(e1), "f"(e0));
            asm("cvt.rn.satfinite.bf16x2.f32 %0, %1, %2;" : "=r"(p23) : "f"(e3), "f"(e2));
            pa[j >> 1][(j & 1) * 2]     = p01;
            pa[j >> 1][(j & 1) * 2 + 1] = p23;
        }

        uint32_t vbase = kvb + 32768;
#pragma unroll
        for (int kc2 = 0; kc2 < 4; kc2++) {
            uint32_t vrow = vbase + (kc2 * 16 + lrow) * 512;
#pragma unroll
            for (int ng = 0; ng < 16; ng++) {
                int u = ng * 2 + lsel;
                int us = (u & ~7) | ((u & 7) ^ xsw);
                uint32_t v4[4];
                ldsm_x4_t(v4, vrow + us * 16);
                mma16816(o[2 * ng],     pa[kc2], v4[0], v4[1]);
                mma16816(o[2 * ng + 1], pa[kc2], v4[2], v4[3]);
            }
        }
        __syncthreads();
    }

    l0 += __shfl_xor_sync(0xffffffffu, l0, 1);
    l0 += __shfl_xor_sync(0xffffffffu, l0, 2);
    l1 += __shfl_xor_sync(0xffffffffu, l1, 1);
    l1 += __shfl_xor_sync(0xffffffffu, l1, 2);
    float i0 = 1.f / l0, i1 = 1.f / l1;

    int gid = lane >> 2, tig = lane & 3;
    int row0 = qt * 128 + warp * 16 + gid;
    __nv_bfloat16* O0 = Oh + ((size_t)b * NHW + row0) * NC;
#pragma unroll
    for (int nt = 0; nt < 32; nt++) {
        uint32_t p0, p1;
        float a0 = o[nt][0] * i0, a1 = o[nt][1] * i0;
        float a2 = o[nt][2] * i1, a3 = o[nt][3] * i1;
        asm("cvt.rn.satfinite.bf16x2.f32 %0, %1, %2;" : "=r"(p0) : "f"(a1), "f"(a0));
        asm("cvt.rn.satfinite.bf16x2.f32 %0, %1, %2;" : "=r"(p1) : "f"(a3), "f"(a2));
        *(uint32_t*)(O0 + nt * 8 + tig * 2) = p0;
        *(uint32_t*)(O0 + 8 * NC + nt * 8 + tig * 2) = p1;
    }
}

// ================= launch =================
extern "C" void kernel_launch(void* const* d_in, const int* in_sizes, int n_in,
                              void* d_out, int out_size) {
    const float* x     = (const float*)d_in[0];
    const float* gamma = (const float*)d_in[1];
    const float* beta  = (const float*)d_in[2];
    const float* wq    = (const float*)d_in[3];
    const float* bq    = (const float*)d_in[4];
    const float* wk    = (const float*)d_in[5];
    const float* bk    = (const float*)d_in[6];
    const float* wv    = (const float*)d_in[7];
    const float* bv    = (const float*)d_in[8];
    const float* wp    = (const float*)d_in[9];
    const float* bp    = (const float*)d_in[10];
    float* out = (float*)d_out;

    __nv_bfloat16 *p_attnh, *p_qh, *p_kh, *p_vh, *p_wh;
    cudaGetSymbolAddress((void**)&p_attnh, g_attnh);
    cudaGetSymbolAddress((void**)&p_qh,    g_qh);
    cudaGetSymbolAddress((void**)&p_kh,    g_kh);
    cudaGetSymbolAddress((void**)&p_vh,    g_vh);
    cudaGetSymbolAddress((void**)&p_wh,    g_wh);

    cudaFuncSetAttribute(flash_mma, cudaFuncAttributeMaxDynamicSharedMemorySize, FL_SMEM);
    cudaFuncSetAttribute(qkv_tc,    cudaFuncAttributeMaxDynamicSharedMemorySize, QKV_SMEM);
    cudaFuncSetAttribute(gemm_tc,   cudaFuncAttributeMaxDynamicSharedMemorySize, GT_SMEM);

    gn_stats_convw<<<512, 256>>>(x, wq, wk, wv, wp);

    qkv_tc<<<128, 256, QKV_SMEM>>>(x, gamma, beta, p_wh, bq, bk, bv, p_qh, p_kh, p_vh);

    flash_mma<<<dim3(32, 4), 256, FL_SMEM>>>(p_qh, p_kh, p_vh, p_attnh);

    gemm_tc<<<128, 256, GT_SMEM>>>(p_attnh, p_wh + 196608, bp, x, out);
}